// round 8
// baseline (speedup 1.0000x reference)
#include <cuda_runtime.h>
#include <cstdint>

// ---------------- problem constants ----------------
#define NB 4
#define CDIM 384
#define CQ 192
#define IH 256
#define IW 256
#define H2 128
#define W2 128
#define NHEADS 8
#define HD 24
#define ATT_SCALE 0.2041241452319315f   // 24^-0.5

constexpr int HW  = IH * IW;   // 65536
constexpr int HW2 = H2 * W2;   // 16384

// ---------------- scratch (device globals; no runtime alloc) ----------------
__device__ float g_We[CDIM * CDIM];          // DWT-folded kv weights (plain)
__device__ float g_We2[CDIM * CDIM];         // fragment-order, tf32
__device__ float g_qw[CQ * CDIM];            // fragment-order, tf32
__device__ float g_pw[CDIM * CQ];            // fragment-order, tf32
__device__ float g_qfeat[(size_t)NB * CQ * HW];
__device__ float g_kv[(size_t)NB * CDIM * HW2];
__device__ float g_feat[(size_t)NB * CQ * HW];

// ---------------- helpers ----------------
__device__ __forceinline__ uint32_t f2tf32(float f) {
    uint32_t r;
    asm("cvt.rna.tf32.f32 %0, %1;" : "=r"(r) : "f"(f));
    return r;
}
__device__ __forceinline__ uint32_t smem_u32(const void* p) {
    uint32_t a;
    asm("{ .reg .u64 t; cvta.to.shared.u64 t, %1; cvt.u32.u64 %0, t; }" : "=r"(a) : "l"(p));
    return a;
}
__device__ __forceinline__ void cp_async16(uint32_t dst, const float* src) {
    asm volatile("cp.async.ca.shared.global [%0], [%1], 16;"
                 :: "r"(dst), "l"(__cvta_generic_to_global(src)));
}
#define CP_COMMIT() asm volatile("cp.async.commit_group;" ::: "memory")
#define CP_WAIT0()  asm volatile("cp.async.wait_group 0;"  ::: "memory")
#define CP_WAIT1()  asm volatile("cp.async.wait_group 1;"  ::: "memory")

// m16n8k8 tf32 mma (baseline PTX, sm_80+)
__device__ __forceinline__ void mma8(float* c, const uint32_t* a, const uint32_t* b) {
    asm volatile(
        "mma.sync.aligned.m16n8k8.row.col.f32.tf32.tf32.f32 "
        "{%0,%1,%2,%3}, {%4,%5,%6,%7}, {%8,%9}, {%0,%1,%2,%3};"
        : "+f"(c[0]), "+f"(c[1]), "+f"(c[2]), "+f"(c[3])
        : "r"(a[0]), "r"(a[1]), "r"(a[2]), "r"(a[3]), "r"(b[0]), "r"(b[1]));
}

// ---------------- prep: fold Haar DWT into kv weights (plain layout) ----------------
__global__ void prep_we_kernel(const float* __restrict__ kvw) {
    int idx = blockIdx.x * blockDim.x + threadIdx.x;
    if (idx >= CDIM * CDIM) return;
    int ch  = idx / CDIM;
    int rem = idx - ch * CDIM;
    int c4  = rem & ~3;
    int pos = rem & 3;
    const float* w = kvw + (size_t)ch * CDIM + c4;
    float a = w[0], b = w[1], c = w[2], d = w[3];
    float r;
    if      (pos == 0) r = 0.5f * ( a - b - c + d);
    else if (pos == 1) r = 0.5f * ( a - b + c - d);
    else if (pos == 2) r = 0.5f * ( a + b - c - d);
    else               r = 0.5f * ( a + b + c + d);
    g_We[idx] = r;
}

// ---------------- prep: rearrange weights into mma-fragment order + tf32 round ----
// dst chunk layout per M-block: [chunk c][tile = wmi*4+ks][lane][4 regs]
// reg order: {(g,tig), (g+8,tig), (g,tig+4), (g+8,tig+4)}
template<int BM, int KTOT>
__global__ void prep_arrange(const float* __restrict__ src, float* __restrict__ dst, int mtot) {
    int idx = blockIdx.x * blockDim.x + threadIdx.x;
    if (idx >= mtot * KTOT) return;
    int mblk = idx / (BM * KTOT);
    int r    = idx % (BM * KTOT);
    int c    = r / (BM * 32);
    int t    = r % (BM * 32);
    int tile = t >> 7;
    int lane = (t >> 2) & 31;
    int qq   = t & 3;
    int wmi = tile >> 2, ks = tile & 3;
    int row = mblk * BM + wmi * 16 + (lane >> 2) + (qq & 1) * 8;
    int kk  = c * 32 + ks * 8 + (lane & 3) + (qq >> 1) * 4;
    dst[idx] = __uint_as_float(f2tf32(src[(size_t)row * KTOT + kk]));
}

// ---------------- tf32 mma.sync GEMM: Y[m,n] = sum_k W[m,k] X[k,n] (+bias) ----------------
// A: fragment-order gmem -> linear cp.async -> LDS.128 fragments.
// B (MODE 0): raw rows cp.async -> smem [32][68]; tf32 cvt at fragment load.
// B (MODE 1): kv DWT gather, register-staged (coalesced row loads).
// 3-stage cp.async pipeline, one syncthreads per chunk. 2 CTA/SM.
template<int WARPS_M, int KTOT, int MODE, int MTOT, bool BIAS>
__global__ __launch_bounds__(256, 2) void mma_gemm(
    const float* __restrict__ Wt, const float* __restrict__ X,
    float* __restrict__ Y, const float* __restrict__ bias, int N)
{
    constexpr int BM      = 48 * WARPS_M;
    constexpr int WARPS_N = 8 / WARPS_M;
    constexpr int WN      = 64 / WARPS_N;   // 32 or 16
    constexpr int NTW     = WN / 8;         // 4 or 2
    constexpr int MT      = 3;
    constexpr int NCH     = KTOT / 32;
    constexpr int MBLKS   = MTOT / BM;
    constexpr int ANF     = BM / 32;        // 16B cp.async per thread for A
    constexpr int AFL     = BM * 32;        // A floats per buffer (fragment order)
    constexpr int BUFL    = AFL + 32 * 68;

    extern __shared__ __align__(16) float sm[];
    const uint32_t sbase = smem_u32(sm);
    const int tid = threadIdx.x, wid = tid >> 5, lane = tid & 31;
    const int wm = wid / WARPS_N, wn = wid % WARPS_N;
    const int g = lane >> 2, tig = lane & 3;

    int mblk, nblk;
    if (MBLKS > 1) { mblk = blockIdx.x; nblk = blockIdx.y; }
    else           { mblk = 0;          nblk = blockIdx.x; }
    const int n0 = nblk * 64;

    const float *Wp, *Xp;
    float* Yp;
    const float* bp = bias;
    int y2 = 0, xb = 0;

    if (MODE == 0) {
        int b = blockIdx.z;
        Wp = Wt + (size_t)mblk * BM * KTOT;
        Xp = X + (size_t)b * KTOT * N;
        Yp = Y + ((size_t)b * MTOT + mblk * BM) * N;
        if (BIAS) bp = bias + mblk * BM;
    } else {
        int b = blockIdx.z >> 2, gg = blockIdx.z & 3;
        Wp = Wt + (size_t)gg * BM * KTOT;
        Xp = X + ((size_t)b * CDIM + gg * 96) * HW;
        Yp = Y + ((size_t)b * CDIM + gg * 96) * HW2;
        y2 = n0 >> 7; xb = n0 & 127;
    }

    float acc[MT][NTW][4] = {};
    float bS[8];

    auto loadA = [&](int c, int buf) {
        const uint32_t As = sbase + (uint32_t)buf * BUFL * 4;
        const float* src = Wp + (size_t)c * AFL;
        #pragma unroll
        for (int i = 0; i < ANF; i++) {
            int e = tid + i * 256;
            cp_async16(As + e * 16, src + e * 4);
        }
    };

    auto loadB0 = [&](int c, int buf) {   // MODE 0: raw fp32 rows
        const int k0 = c * 32;
        const uint32_t Bs = sbase + ((uint32_t)buf * BUFL + AFL) * 4;
        #pragma unroll
        for (int i = 0; i < 2; i++) {
            int e = tid + i * 256;
            int kr = e >> 4, n4 = (e & 15) * 4;
            cp_async16(Bs + (kr * 68 + n4) * 4, Xp + (size_t)(k0 + kr) * N + n0 + n4);
        }
    };

    auto loadB1 = [&](int c) {            // MODE 1: DWT gather, coalesced
        const int crel0 = c * 8;
        #pragma unroll
        for (int i = 0; i < 8; i++) {
            int e = tid + i * 256;
            int ch = e >> 8, row = (e >> 7) & 1, col = e & 127;
            bS[i] = Xp[(size_t)(crel0 + ch) * HW + (2 * y2 + row) * IW + 2 * xb + col];
        }
    };

    auto storeB1 = [&](int buf) {
        uint32_t* Bs = (uint32_t*)(sm + buf * BUFL + AFL);
        #pragma unroll
        for (int i = 0; i < 8; i++) {
            int e = tid + i * 256;
            int ch = e >> 8, row = (e >> 7) & 1, col = e & 127;
            int k = ch * 4 + row * 2 + (col & 1);
            int n = col >> 1;
            Bs[k * 68 + n] = f2tf32(bS[i]);
        }
    };

    auto compute = [&](int buf) {
        const uint32_t* As = (const uint32_t*)(sm + buf * BUFL);
        const float*    Bf = sm + buf * BUFL + AFL;
        #pragma unroll
        for (int ks = 0; ks < 4; ks++) {
            uint32_t a[MT][4], b[NTW][2];
            #pragma unroll
            for (int i = 0; i < MT; i++) {
                uint4 v = *(const uint4*)(As + (((wm * 3 + i) * 4 + ks) * 32 + lane) * 4);
                a[i][0] = v.x; a[i][1] = v.y; a[i][2] = v.z; a[i][3] = v.w;
            }
            #pragma unroll
            for (int j = 0; j < NTW; j++) {
                const float* p = Bf + (ks * 8 + tig) * 68 + wn * WN + j * 8 + g;
                b[j][0] = f2tf32(p[0]);
                b[j][1] = f2tf32(p[4 * 68]);
            }
            #pragma unroll
            for (int i = 0; i < MT; i++)
                #pragma unroll
                for (int j = 0; j < NTW; j++)
                    mma8(acc[i][j], a[i], b[j]);
        }
    };

    // ---- 3-stage pipeline ----
    if (MODE == 0) {
        loadA(0, 0); loadB0(0, 0); CP_COMMIT();
        loadA(1, 1); loadB0(1, 1); CP_COMMIT();
        #pragma unroll 4
        for (int c = 0; c < NCH; c++) {
            if (c + 2 < NCH) {
                CP_WAIT1();
                __syncthreads();
                loadA(c + 2, (c + 2) % 3);
                loadB0(c + 2, (c + 2) % 3);
                CP_COMMIT();
            } else if (c + 2 == NCH) {
                CP_WAIT0();
                __syncthreads();
            }
            compute(c % 3);
        }
    } else {
        loadA(0, 0); CP_COMMIT();
        loadA(1, 1); CP_COMMIT();
        loadB1(0); storeB1(0);
        loadB1(1);
        #pragma unroll 4
        for (int c = 0; c < NCH; c++) {
            if (c + 2 < NCH) {
                CP_WAIT1();
                __syncthreads();
                loadA(c + 2, (c + 2) % 3);
                CP_COMMIT();
                storeB1((c + 1) % 3);
                loadB1(c + 2);
            } else if (c + 2 == NCH) {
                CP_WAIT0();
                __syncthreads();
                storeB1((c + 1) % 3);
            } else {
                __syncthreads();
            }
            compute(c % 3);
        }
    }

    // ---- epilogue ----
    const int mb = wm * 48;
    const int nb = n0 + wn * WN;
    #pragma unroll
    for (int i = 0; i < MT; i++) {
        int r0 = mb + i * 16 + g;
        float b0 = 0.f, b1 = 0.f;
        if (BIAS) { b0 = bp[r0]; b1 = bp[r0 + 8]; }
        #pragma unroll
        for (int j = 0; j < NTW; j++) {
            int nc = nb + j * 8 + tig * 2;
            *(float2*)(Yp + (size_t)r0 * N + nc) =
                make_float2(acc[i][j][0] + b0, acc[i][j][1] + b0);
            *(float2*)(Yp + (size_t)(r0 + 8) * N + nc) =
                make_float2(acc[i][j][2] + b1, acc[i][j][3] + b1);
        }
    }
}

// ---------------- attention: bilinear, register-blocked ----------------
constexpr int KS_F = 192 * 17;
constexpr int MS_F = 24 * 200;
constexpr int ATTN_SMEM = (2 * KS_F + MS_F) * 4;   // 45312 B

__global__ __launch_bounds__(256, 3) void attn_kernel()
{
    extern __shared__ float sm[];
    float* ks = sm;
    float* vs = ks + KS_F;
    float* Ms = vs + KS_F;

    const int w = blockIdx.x;
    const int b  = w >> 10;
    const int wl = w & 1023;
    const int wy = wl >> 5, wx = wl & 31;
    const int tid = threadIdx.x;

    const float* kvb = g_kv + (size_t)b * CDIM * HW2;
    #pragma unroll
    for (int i = 0; i < 12; i++) {
        int e = tid + i * 256;
        int ch = e >> 4, t = e & 15;
        int y2 = wy * 4 + (t >> 2), x2 = wx * 4 + (t & 3);
        size_t off = (size_t)ch * HW2 + y2 * W2 + x2;
        ks[ch * 17 + t] = kvb[off];
        vs[ch * 17 + t] = kvb[off + (size_t)CQ * HW2];
    }
    __syncthreads();

    {
        const int h = tid >> 5, lane = tid & 31;
        const int e0 = (lane >> 2) * 3, d0 = (lane & 3) * 6;
        float acc[3][6] = {};
        const float* kp = ks + (h * 24 + e0) * 17;
        const float* vp = vs + (h * 24 + d0) * 17;
        #pragma unroll
        for (int t = 0; t < 16; t++) {
            float kk[3], vv[6];
            #pragma unroll
            for (int i = 0; i < 3; i++) kk[i] = kp[i * 17 + t];
            #pragma unroll
            for (int j = 0; j < 6; j++) vv[j] = vp[j * 17 + t];
            #pragma unroll
            for (int i = 0; i < 3; i++)
                #pragma unroll
                for (int j = 0; j < 6; j++)
                    acc[i][j] = fmaf(kk[i], vv[j], acc[i][j]);
        }
        #pragma unroll
        for (int i = 0; i < 3; i++)
            #pragma unroll
            for (int j = 0; j < 6; j++)
                Ms[(e0 + i) * 200 + h * 25 + d0 + j] = acc[i][j] * ATT_SCALE;
    }
    __syncthreads();

    {
        const int q4 = tid >> 4;
        const int h  = (tid >> 1) & 7;
        const int dh = tid & 1;
        const int p0 = q4 * 4;
        const int y = wy * 8 + (p0 >> 3), x = wx * 8 + (p0 & 7);
        float acc[4][12] = {};
        const float* qp = g_qfeat + ((size_t)b * CQ + h * 24) * HW + y * IW + x;
        const float* mp = Ms + h * 25 + dh * 12;
        #pragma unroll
        for (int e = 0; e < 24; e++) {
            float4 qv = *(const float4*)(qp + (size_t)e * HW);
            float q0 = qv.x, q1 = qv.y, q2 = qv.z, q3 = qv.w;
            #pragma unroll
            for (int j = 0; j < 12; j++) {
                float mv = mp[e * 200 + j];
                acc[0][j] = fmaf(q0, mv, acc[0][j]);
                acc[1][j] = fmaf(q1, mv, acc[1][j]);
                acc[2][j] = fmaf(q2, mv, acc[2][j]);
                acc[3][j] = fmaf(q3, mv, acc[3][j]);
            }
        }
        float* fb = g_feat + ((size_t)b * CQ + h * 24 + dh * 12) * HW + y * IW + x;
        #pragma unroll
        for (int j = 0; j < 12; j++) {
            *(float4*)(fb + (size_t)j * HW) =
                make_float4(acc[0][j], acc[1][j], acc[2][j], acc[3][j]);
        }
    }
}

// ---------------- launch ----------------
extern "C" void kernel_launch(void* const* d_in, const int* in_sizes, int n_in,
                              void* d_out, int out_size) {
    const float* x      = (const float*)d_in[0];
    const float* q_w    = (const float*)d_in[1];
    const float* kv_w   = (const float*)d_in[2];
    const float* proj_w = (const float*)d_in[3];
    const float* proj_b = (const float*)d_in[4];
    float* out = (float*)d_out;

    float *qf, *kv, *ft, *we, *we2, *qw, *pw;
    cudaGetSymbolAddress((void**)&qf, g_qfeat);
    cudaGetSymbolAddress((void**)&kv, g_kv);
    cudaGetSymbolAddress((void**)&ft, g_feat);
    cudaGetSymbolAddress((void**)&we, g_We);
    cudaGetSymbolAddress((void**)&we2, g_We2);
    cudaGetSymbolAddress((void**)&qw, g_qw);
    cudaGetSymbolAddress((void**)&pw, g_pw);

    auto kq = mma_gemm<4, 384, 0, 192, false>;   // q:    BM=192, K=384
    auto kk = mma_gemm<2, 384, 1,  96, false>;   // kv:   BM=96,  K=384, DWT gather
    auto kp = mma_gemm<4, 192, 0, 384, true>;    // proj: 2 M-blocks, K=192, bias

    const int smem_q  = 3 * (192 * 32 + 32 * 68) * 4;  // 99840
    const int smem_kv = 3 * ( 96 * 32 + 32 * 68) * 4;  // 62976
    const int smem_pj = smem_q;
    cudaFuncSetAttribute(kq, cudaFuncAttributeMaxDynamicSharedMemorySize, smem_q);
    cudaFuncSetAttribute(kk, cudaFuncAttributeMaxDynamicSharedMemorySize, smem_kv);
    cudaFuncSetAttribute(kp, cudaFuncAttributeMaxDynamicSharedMemorySize, smem_pj);
    cudaFuncSetAttribute(attn_kernel, cudaFuncAttributeMaxDynamicSharedMemorySize, ATTN_SMEM);

    prep_we_kernel<<<(CDIM * CDIM + 255) / 256, 256>>>(kv_w);
    prep_arrange<192, 384><<<(CQ * CDIM + 255) / 256, 256>>>(q_w, qw, CQ);
    prep_arrange<192, 192><<<(CDIM * CQ + 255) / 256, 256>>>(proj_w, pw, CDIM);
    prep_arrange< 96, 384><<<(CDIM * CDIM + 255) / 256, 256>>>(we, we2, CDIM);

    kq<<<dim3(HW / 64, 1, NB),      256, smem_q >>>(qw, x, qf, nullptr, HW);
    kk<<<dim3(HW2 / 64, 1, NB * 4), 256, smem_kv>>>(we2, x, kv, nullptr, HW2);
    attn_kernel<<<NB * 1024, 256, ATTN_SMEM>>>();
    kp<<<dim3(2, HW / 64, NB),      256, smem_pj>>>(pw, ft, out, proj_b, HW);
}